// round 16
// baseline (speedup 1.0000x reference)
#include <cuda_runtime.h>
#include <cstdint>

// Covariance pooling: y[b] = (1/M) X Xᵀ - μ μᵀ, X = x[b] as [C=128, M=4096].
// R13 (best: tf32 mma.sync, KSPLIT=4, occupancy 2) with KT widened 32->64 and
// a 2-stage pipeline: halves per-unit loop/sync/cp_wait overhead and doubles
// per-iteration ILP. Structure, math, and finish kernel identical to R13.
// Kernel 1 (partial): 256 CTAs = 64 batches x 4 K-quarters; 128 threads; 4
//   warps of 64x64 tiles; cp.async 2-stage double buffer (68 KB smem -> 2
//   CTAs/SM); raw-fp32 into tf32 mma.sync (debias CORR); exact fp32 row sums.
// Kernel 2 (finish): 512 CTAs combine 4 K-quarters + mean subtraction.

#define DINLINE __device__ __forceinline__

static constexpr int Bn = 64;
static constexpr int Cn = 128;
static constexpr int Mn = 4096;
static constexpr int KSPLIT = 4;
static constexpr int KQ = Mn / KSPLIT;     // 1024
static constexpr int KT = 64;              // k floats per tile (256 B per row)
static constexpr int NKT = KQ / KT;        // 16 tiles
static constexpr int PADB = 272;           // bytes per SMEM row (256 + 16 pad)
static constexpr int STAGES = 2;
static constexpr int STAGE_B = Cn * PADB;  // 34816
static constexpr int SMEM_B = STAGES * STAGE_B;  // 69632 -> 2 CTAs/SM fit

// tf32 truncation debias: 1/(1 - 2 * 2^-11 * (1/(2 ln 2)))
static constexpr float CORR = 1.00070466f;

__device__ float g_part[KSPLIT * Bn][Cn * Cn];   // 16 MB scratch
__device__ float g_sums[KSPLIT * Bn][Cn];

DINLINE void mma_tf32(float d[4], const uint32_t a[4], uint32_t b0, uint32_t b1) {
    asm volatile(
        "mma.sync.aligned.m16n8k8.row.col.f32.tf32.tf32.f32 "
        "{%0,%1,%2,%3}, {%4,%5,%6,%7}, {%8,%9}, {%0,%1,%2,%3};"
        : "+f"(d[0]), "+f"(d[1]), "+f"(d[2]), "+f"(d[3])
        : "r"(a[0]), "r"(a[1]), "r"(a[2]), "r"(a[3]), "r"(b0), "r"(b1));
}
DINLINE void ldsm_x4(uint32_t r[4], uint32_t addr) {
    asm volatile("ldmatrix.sync.aligned.m8n8.x4.shared.b16 {%0,%1,%2,%3}, [%4];"
                 : "=r"(r[0]), "=r"(r[1]), "=r"(r[2]), "=r"(r[3]) : "r"(addr));
}
DINLINE uint32_t smem_u32(const void* p) {
    uint32_t a;
    asm("{ .reg .u64 t; cvta.to.shared.u64 t, %1; cvt.u32.u64 %0, t; }"
        : "=r"(a) : "l"(p));
    return a;
}
DINLINE void cp16(uint32_t dst, const void* src) {
    asm volatile("cp.async.cg.shared.global [%0], [%1], 16;"
                 :: "r"(dst), "l"(src) : "memory");
}
DINLINE void cp_commit() { asm volatile("cp.async.commit_group;" ::: "memory"); }
template <int N> DINLINE void cp_wait() {
    asm volatile("cp.async.wait_group %0;" :: "n"(N) : "memory");
}

__global__ __launch_bounds__(128, 2)
void covpool_partial(const float* __restrict__ x) {
    extern __shared__ char smem[];
    const uint32_t sb = smem_u32(smem);

    const int t    = threadIdx.x;
    const int warp = t >> 5;
    const int lane = t & 31;
    const int cta  = blockIdx.x;        // 0..255
    const int s    = cta & 3;           // K-quarter
    const int b    = cta >> 2;

    // loader: one row per thread, 256 B per k-tile
    const float* xrow = x + (size_t)b * Cn * Mn + (size_t)t * Mn + (size_t)s * KQ;
    const uint32_t ldst = (uint32_t)(t * PADB);

    // warp tile 64x64, 2x2 warp grid
    const int wm = (warp & 1) * 64;
    const int wn = (warp >> 1) * 64;
    const int g  = lane >> 2;
    const int tg = lane & 3;

    const uint32_t aoff = (uint32_t)((wm + (lane & 15)) * PADB + (lane >> 4) * 16);
    const uint32_t boff = (uint32_t)((wn + (lane & 7) + ((lane >> 4) * 8)) * PADB
                                     + ((lane >> 3) & 1) * 16);

    float acc[4][8][4];
#pragma unroll
    for (int im = 0; im < 4; im++)
#pragma unroll
        for (int in = 0; in < 8; in++)
#pragma unroll
            for (int j = 0; j < 4; j++) acc[im][in][j] = 0.0f;

    float rowsum = 0.0f;

    auto issue = [&](int kt_) {         // cp.async tile kt_ into stage kt_&1
        const uint32_t d0 = sb + (uint32_t)((kt_ & 1) * STAGE_B) + ldst;
        const float* src = xrow + (size_t)kt_ * KT;
#pragma unroll
        for (int i = 0; i < 16; i++) cp16(d0 + i * 16, src + i * 4);
        cp_commit();
    };

    // prologue: tiles 0,1 in flight
    issue(0);
    issue(1);

    for (int kt = 0; kt < NKT; kt++) {
        if (kt + 1 < NKT) cp_wait<1>(); else cp_wait<0>();
        __syncthreads();

        const int cur = kt & 1;
        const uint32_t base = sb + (uint32_t)(cur * STAGE_B);

        // exact fp32 row sum of this thread's own row
#pragma unroll
        for (int i = 0; i < 16; i++) {
            float4 v = *(const float4*)(smem + cur * STAGE_B + t * PADB + i * 16);
            rowsum += v.x + v.y + v.z + v.w;
        }

#pragma unroll
        for (int ks = 0; ks < 8; ks++) {
            const uint32_t k0 = (uint32_t)(ks * 32);   // bytes within row
            uint32_t A[4][4], Bf[4][4];
#pragma unroll
            for (int im = 0; im < 4; im++)
                ldsm_x4(A[im], base + aoff + im * 16 * PADB + k0);
#pragma unroll
            for (int jn = 0; jn < 4; jn++)
                ldsm_x4(Bf[jn], base + boff + jn * 16 * PADB + k0);
#pragma unroll
            for (int im = 0; im < 4; im++)
#pragma unroll
                for (int jn = 0; jn < 4; jn++) {
                    mma_tf32(acc[im][2 * jn],     A[im], Bf[jn][0], Bf[jn][1]);
                    mma_tf32(acc[im][2 * jn + 1], A[im], Bf[jn][2], Bf[jn][3]);
                }
        }

        __syncthreads();                 // everyone done reading stage cur
        if (kt + 2 < NKT) issue(kt + 2); // refill it 2 ahead
    }

    // epilogue: partial Gram + row sums to scratch
    float* gp = g_part[cta];
#pragma unroll
    for (int im = 0; im < 4; im++) {
        const int r0 = wm + im * 16 + g;
#pragma unroll
        for (int in = 0; in < 8; in++) {
            const int c0 = wn + in * 8 + 2 * tg;
            *(float2*)(gp + (size_t)r0 * Cn + c0) =
                make_float2(acc[im][in][0], acc[im][in][1]);
            *(float2*)(gp + (size_t)(r0 + 8) * Cn + c0) =
                make_float2(acc[im][in][2], acc[im][in][3]);
        }
    }
    g_sums[cta][t] = rowsum;
}

__global__ __launch_bounds__(256, 2)
void covpool_finish(float* __restrict__ y) {
    __shared__ float mu[Cn];
    const int t   = threadIdx.x;
    const int b   = blockIdx.x >> 3;
    const int q   = blockIdx.x & 7;
    if (t < Cn)
        mu[t] = (g_sums[4 * b][t] + g_sums[4 * b + 1][t]
               + g_sums[4 * b + 2][t] + g_sums[4 * b + 3][t]) * (1.0f / (float)Mn);
    __syncthreads();

    const float4* G0 = (const float4*)g_part[4 * b];
    const float4* G1 = (const float4*)g_part[4 * b + 1];
    const float4* G2 = (const float4*)g_part[4 * b + 2];
    const float4* G3 = (const float4*)g_part[4 * b + 3];
    float4* out = (float4*)(y + (size_t)b * Cn * Cn);
    const float4* mu4 = (const float4*)mu;
    const float a = CORR * (1.0f / (float)Mn);
#pragma unroll
    for (int j = 0; j < 2; j++) {
        const int idx = q * 512 + t + j * 256;    // float4 index in [0,4096)
        const int r   = idx >> 5;
        const float mr = mu[r];
        const float4 m = mu4[idx & 31];
        const float4 p0 = G0[idx];
        const float4 p1 = G1[idx];
        const float4 p2 = G2[idx];
        const float4 p3 = G3[idx];
        float4 o;
        o.x = ((p0.x + p1.x) + (p2.x + p3.x)) * a - mr * m.x;
        o.y = ((p0.y + p1.y) + (p2.y + p3.y)) * a - mr * m.y;
        o.z = ((p0.z + p1.z) + (p2.z + p3.z)) * a - mr * m.z;
        o.w = ((p0.w + p1.w) + (p2.w + p3.w)) * a - mr * m.w;
        out[idx] = o;
    }
}

extern "C" void kernel_launch(void* const* d_in, const int* in_sizes, int n_in,
                              void* d_out, int out_size) {
    (void)in_sizes; (void)n_in; (void)out_size;
    const float* x = (const float*)d_in[0];
    float* y = (float*)d_out;
    cudaFuncSetAttribute(covpool_partial,
                         cudaFuncAttributeMaxDynamicSharedMemorySize, SMEM_B);
    covpool_partial<<<KSPLIT * Bn, 128, SMEM_B>>>(x);
    covpool_finish<<<8 * Bn, 256>>>(y);
}

// round 17
// speedup vs baseline: 1.0842x; 1.0842x over previous
#include <cuda_runtime.h>
#include <cstdint>

// Covariance pooling: y[b] = (1/M) X Xᵀ - μ μᵀ, X = x[b] as [C=128, M=4096].
// R13 (best: tf32 mma.sync, KSPLIT=4, occupancy 2) + two surgical tweaks:
//   1. 4-stage cp.async pipeline (cp_wait<2>): ~2 tile-periods of load flight.
//   2. MMA block issues FIRST after the sync; the rowsum LDS pass runs after,
//      in the shadow of the MMA tail (stage cur is not rewritten until iss =
//      (kt+3)&3 != cur, so the late read is race-free).
// Kernel 1 (partial): 256 CTAs = 64 batches x 4 K-quarters; 128 threads; 4
//   warps of 64x64 tiles; raw-fp32 into tf32 mma.sync (debias CORR); exact
//   fp32 row sums in-pipeline.
// Kernel 2 (finish): 512 CTAs combine 4 K-quarters + mean subtraction.

#define DINLINE __device__ __forceinline__

static constexpr int Bn = 64;
static constexpr int Cn = 128;
static constexpr int Mn = 4096;
static constexpr int KSPLIT = 4;
static constexpr int KQ = Mn / KSPLIT;     // 1024
static constexpr int KT = 32;              // k floats per tile
static constexpr int NKT = KQ / KT;        // 32 tiles
static constexpr int PADB = 144;           // bytes per SMEM row (36 floats)
static constexpr int STAGES = 4;
static constexpr int STAGE_B = Cn * PADB;  // 18432
static constexpr int SMEM_B = STAGES * STAGE_B;  // 73728 -> 2 CTAs/SM fit

// tf32 truncation debias: 1/(1 - 2 * 2^-11 * (1/(2 ln 2)))
static constexpr float CORR = 1.00070466f;

__device__ float g_part[KSPLIT * Bn][Cn * Cn];   // 16 MB scratch
__device__ float g_sums[KSPLIT * Bn][Cn];

DINLINE void mma_tf32(float d[4], const uint32_t a[4], uint32_t b0, uint32_t b1) {
    asm volatile(
        "mma.sync.aligned.m16n8k8.row.col.f32.tf32.tf32.f32 "
        "{%0,%1,%2,%3}, {%4,%5,%6,%7}, {%8,%9}, {%0,%1,%2,%3};"
        : "+f"(d[0]), "+f"(d[1]), "+f"(d[2]), "+f"(d[3])
        : "r"(a[0]), "r"(a[1]), "r"(a[2]), "r"(a[3]), "r"(b0), "r"(b1));
}
DINLINE void ldsm_x4(uint32_t r[4], uint32_t addr) {
    asm volatile("ldmatrix.sync.aligned.m8n8.x4.shared.b16 {%0,%1,%2,%3}, [%4];"
                 : "=r"(r[0]), "=r"(r[1]), "=r"(r[2]), "=r"(r[3]) : "r"(addr));
}
DINLINE uint32_t smem_u32(const void* p) {
    uint32_t a;
    asm("{ .reg .u64 t; cvta.to.shared.u64 t, %1; cvt.u32.u64 %0, t; }"
        : "=r"(a) : "l"(p));
    return a;
}
DINLINE void cp16(uint32_t dst, const void* src) {
    asm volatile("cp.async.cg.shared.global [%0], [%1], 16;"
                 :: "r"(dst), "l"(src) : "memory");
}
DINLINE void cp_commit() { asm volatile("cp.async.commit_group;" ::: "memory"); }
template <int N> DINLINE void cp_wait() {
    asm volatile("cp.async.wait_group %0;" :: "n"(N) : "memory");
}

__global__ __launch_bounds__(128, 2)
void covpool_partial(const float* __restrict__ x) {
    extern __shared__ char smem[];
    const uint32_t sb = smem_u32(smem);

    const int t    = threadIdx.x;
    const int warp = t >> 5;
    const int lane = t & 31;
    const int cta  = blockIdx.x;        // 0..255
    const int s    = cta & 3;           // K-quarter
    const int b    = cta >> 2;

    // loader: one row per thread, 128 B per k-tile
    const float* xrow = x + (size_t)b * Cn * Mn + (size_t)t * Mn + (size_t)s * KQ;
    const uint32_t ldst = (uint32_t)(t * PADB);

    // warp tile 64x64, 2x2 warp grid
    const int wm = (warp & 1) * 64;
    const int wn = (warp >> 1) * 64;
    const int g  = lane >> 2;
    const int tg = lane & 3;

    const uint32_t aoff = (uint32_t)((wm + (lane & 15)) * PADB + (lane >> 4) * 16);
    const uint32_t boff = (uint32_t)((wn + (lane & 7) + ((lane >> 4) * 8)) * PADB
                                     + ((lane >> 3) & 1) * 16);

    float acc[4][8][4];
#pragma unroll
    for (int im = 0; im < 4; im++)
#pragma unroll
        for (int in = 0; in < 8; in++)
#pragma unroll
            for (int j = 0; j < 4; j++) acc[im][in][j] = 0.0f;

    float rowsum = 0.0f;

    // prologue: stages 0..2
#pragma unroll
    for (int p = 0; p < STAGES - 1; p++) {
        const uint32_t d0 = sb + p * STAGE_B + ldst;
        const float* src = xrow + p * KT;
#pragma unroll
        for (int i = 0; i < 8; i++) cp16(d0 + i * 16, src + i * 4);
        cp_commit();
    }

    int cur = 0, iss = STAGES - 1;
    for (int kt = 0; kt < NKT; kt++) {
        cp_wait<STAGES - 2>();
        __syncthreads();
        if (kt + STAGES - 1 < NKT) {
            const uint32_t d0 = sb + iss * STAGE_B + ldst;
            const float* src = xrow + (kt + STAGES - 1) * KT;
#pragma unroll
            for (int i = 0; i < 8; i++) cp16(d0 + i * 16, src + i * 4);
        }
        cp_commit();

        const uint32_t base = sb + cur * STAGE_B;

        // ---- MMA first: tensor stream launches at sync release ----
#pragma unroll
        for (int ks = 0; ks < 4; ks++) {
            const uint32_t k0 = ks * 32;   // bytes within row
            uint32_t A[4][4], Bf[4][4];
#pragma unroll
            for (int im = 0; im < 4; im++)
                ldsm_x4(A[im], base + aoff + im * 16 * PADB + k0);
#pragma unroll
            for (int jn = 0; jn < 4; jn++)
                ldsm_x4(Bf[jn], base + boff + jn * 16 * PADB + k0);
#pragma unroll
            for (int im = 0; im < 4; im++)
#pragma unroll
                for (int jn = 0; jn < 4; jn++) {
                    mma_tf32(acc[im][2 * jn],     A[im], Bf[jn][0], Bf[jn][1]);
                    mma_tf32(acc[im][2 * jn + 1], A[im], Bf[jn][2], Bf[jn][3]);
                }
        }

        // ---- rowsum after: drains in the MMA tail's shadow (stage cur is
        //      not rewritten until iss=(kt+3)&3 != cur) ----
#pragma unroll
        for (int i = 0; i < 8; i++) {
            float4 v = *(const float4*)(smem + cur * STAGE_B + t * PADB + i * 16);
            rowsum += v.x + v.y + v.z + v.w;
        }

        cur = (cur + 1 == STAGES) ? 0 : cur + 1;
        iss = (iss + 1 == STAGES) ? 0 : iss + 1;
    }

    // epilogue: partial Gram + row sums to scratch
    float* gp = g_part[cta];
#pragma unroll
    for (int im = 0; im < 4; im++) {
        const int r0 = wm + im * 16 + g;
#pragma unroll
        for (int in = 0; in < 8; in++) {
            const int c0 = wn + in * 8 + 2 * tg;
            *(float2*)(gp + (size_t)r0 * Cn + c0) =
                make_float2(acc[im][in][0], acc[im][in][1]);
            *(float2*)(gp + (size_t)(r0 + 8) * Cn + c0) =
                make_float2(acc[im][in][2], acc[im][in][3]);
        }
    }
    g_sums[cta][t] = rowsum;
}

__global__ __launch_bounds__(256, 2)
void covpool_finish(float* __restrict__ y) {
    __shared__ float mu[Cn];
    const int t   = threadIdx.x;
    const int b   = blockIdx.x >> 3;
    const int q   = blockIdx.x & 7;
    if (t < Cn)
        mu[t] = (g_sums[4 * b][t] + g_sums[4 * b + 1][t]
               + g_sums[4 * b + 2][t] + g_sums[4 * b + 3][t]) * (1.0f / (float)Mn);
    __syncthreads();

    const float4* G0 = (const float4*)g_part[4 * b];
    const float4* G1 = (const float4*)g_part[4 * b + 1];
    const float4* G2 = (const float4*)g_part[4 * b + 2];
    const float4* G3 = (const float4*)g_part[4 * b + 3];
    float4* out = (float4*)(y + (size_t)b * Cn * Cn);
    const float4* mu4 = (const float4*)mu;
    const float a = CORR * (1.0f / (float)Mn);
#pragma unroll
    for (int j = 0; j < 2; j++) {
        const int idx = q * 512 + t + j * 256;    // float4 index in [0,4096)
        const int r   = idx >> 5;
        const float mr = mu[r];
        const float4 m = mu4[idx & 31];
        const float4 p0 = G0[idx];
        const float4 p1 = G1[idx];
        const float4 p2 = G2[idx];
        const float4 p3 = G3[idx];
        float4 o;
        o.x = ((p0.x + p1.x) + (p2.x + p3.x)) * a - mr * m.x;
        o.y = ((p0.y + p1.y) + (p2.y + p3.y)) * a - mr * m.y;
        o.z = ((p0.z + p1.z) + (p2.z + p3.z)) * a - mr * m.z;
        o.w = ((p0.w + p1.w) + (p2.w + p3.w)) * a - mr * m.w;
        out[idx] = o;
    }
}

extern "C" void kernel_launch(void* const* d_in, const int* in_sizes, int n_in,
                              void* d_out, int out_size) {
    (void)in_sizes; (void)n_in; (void)out_size;
    const float* x = (const float*)d_in[0];
    float* y = (float*)d_out;
    cudaFuncSetAttribute(covpool_partial,
                         cudaFuncAttributeMaxDynamicSharedMemorySize, SMEM_B);
    covpool_partial<<<KSPLIT * Bn, 128, SMEM_B>>>(x);
    covpool_finish<<<8 * Bn, 256>>>(y);
}